// round 6
// baseline (speedup 1.0000x reference)
#include <cuda_runtime.h>
#include <math.h>

#define B_DIM   4096
#define N_GENN  512
#define F_GEN   64
#define EMB     16
#define OUT_ROW 1025
#define THREADS 256
#define CH_ROWS 64            // x rows per staged chunk (16KB)
#define NCHUNK  8
#define STAGES  4
#define CH_FLTS (CH_ROWS * F_GEN)

__device__ __forceinline__ void mma_tf32(float c[4], const unsigned a[4],
                                         unsigned b0, unsigned b1) {
    asm volatile(
        "mma.sync.aligned.m16n8k8.row.col.f32.tf32.tf32.f32 "
        "{%0,%1,%2,%3}, {%4,%5,%6,%7}, {%8,%9}, {%0,%1,%2,%3};"
        : "+f"(c[0]), "+f"(c[1]), "+f"(c[2]), "+f"(c[3])
        : "r"(a[0]), "r"(a[1]), "r"(a[2]), "r"(a[3]), "r"(b0), "r"(b1));
}

__device__ __forceinline__ void ldsm4(unsigned r[4], unsigned addr) {
    asm volatile("ldmatrix.sync.aligned.m8n8.x4.shared.b16 {%0,%1,%2,%3}, [%4];"
                 : "=r"(r[0]), "=r"(r[1]), "=r"(r[2]), "=r"(r[3]) : "r"(addr));
}

__device__ __forceinline__ void cp16(void* smem_dst, const void* gsrc) {
    unsigned s = (unsigned)__cvta_generic_to_shared(smem_dst);
    asm volatile("cp.async.cg.shared.global [%0], [%1], 16;" :: "r"(s), "l"(gsrc));
}
#define CP_COMMIT() asm volatile("cp.async.commit_group;")
#define CP_WAIT(n)  asm volatile("cp.async.wait_group %0;" :: "n"(n))

// Stage one 64-row x chunk, 16B-unit XOR swizzle: unit j of row r -> slot j^(r&7).
// Conflict-free for both the cp.async stores and the ldmatrix gathers.
__device__ __forceinline__ void issue_chunk(float* sbuf, const float* gbase, int t) {
    #pragma unroll
    for (int k = 0; k < 4; k++) {
        int idx = t + THREADS * k;          // 0..1023 16B units
        int r = idx >> 4, j = idx & 15;
        int slot = j ^ (r & 7);
        cp16(&sbuf[r * 64 + slot * 4], gbase + r * 64 + j * 4);
    }
}

extern __shared__ float smem_dyn[];         // [STAGES*CH_FLTS] x-tiles, then sred[8]

__global__ void __launch_bounds__(THREADS, 3)
fused_model_kernel(const float* __restrict__ x_gen,
                   const float* __restrict__ W_gen,
                   const float* __restrict__ b_gen,
                   const float* __restrict__ W_val,
                   const float* __restrict__ b_val,
                   const float* __restrict__ param,
                   const float* __restrict__ high,
                   float* __restrict__ out)
{
    float* sX   = smem_dyn;
    float* sred = smem_dyn + STAGES * CH_FLTS;

    const int b    = blockIdx.x;
    const int t    = threadIdx.x;
    const int warp = t >> 5;
    const int lane = t & 31;
    const int nt   = warp & 1;              // which 8-col n-tile this warp owns
    const int rgrp = warp >> 1;             // which 16-row m-group

    const float* gx = x_gen + (size_t)b * N_GENN * F_GEN;

    // ---- Preload chunks 0..2 immediately (prefetch distance 3)
    issue_chunk(sX + 0 * CH_FLTS, gx, t);                    CP_COMMIT();
    issue_chunk(sX + 1 * CH_FLTS, gx + 1 * CH_FLTS, t);      CP_COMMIT();
    issue_chunk(sX + 2 * CH_FLTS, gx + 2 * CH_FLTS, t);      CP_COMMIT();

    // ---- Action head: out[b, 0..1023] (batch-independent, coalesced)
    {
        const float s0 = 1.0f / (1.0f + expf(-param[0]));
        const float s1 = 0.5f / (1.0f + expf(-param[1]));
        float* orow = out + (size_t)b * OUT_ROW;
        #pragma unroll
        for (int j = 0; j < 4; j++) {
            int i = t + THREADS * j;
            float h = __ldg(&high[i >> 1]);
            orow[i] = (i & 1) ? s1 * h : s0 * h;
        }
    }

    // ---- B fragments for this warp's n-tile: raw fp32 (HW truncates to tf32 = hi)
    //      plus lo = w - trunc(w). 32 regs total.
    unsigned braw[8][2], blo[8][2];
    {
        const int kk = lane & 3, nn = (lane >> 2) + 8 * nt;
        #pragma unroll
        for (int ks = 0; ks < 8; ks++)
            #pragma unroll
            for (int h = 0; h < 2; h++) {
                float w = __ldg(&W_gen[(kk + 4 * h + 8 * ks) * EMB + nn]);
                unsigned whi = __float_as_uint(w) & 0xFFFFE000u;
                braw[ks][h] = __float_as_uint(w);
                blo[ks][h]  = __float_as_uint(w - __uint_as_float(whi));
            }
    }

    // ---- Bias for this thread's C columns: n = 2*(lane&3) + {0,1} + 8*nt
    const float bias0 = __ldg(&b_gen[2 * (lane & 3) + 8 * nt]);
    const float bias1 = __ldg(&b_gen[2 * (lane & 3) + 8 * nt + 1]);

    const int row_local = rgrp * 16 + (lane & 15);
    const int hiu       = lane >> 4;
    const int rxor      = row_local & 7;

    float vpart = 0.0f;

    #pragma unroll 1
    for (int ch = 0; ch < NCHUNK; ch++) {
        float* buf = sX + (ch % STAGES) * CH_FLTS;
        if (ch + 3 < NCHUNK) {
            issue_chunk(sX + ((ch + 3) % STAGES) * CH_FLTS, gx + (ch + 3) * CH_FLTS, t);
            CP_COMMIT();
            CP_WAIT(3);
        } else {
            if      (ch == NCHUNK - 3) CP_WAIT(2);
            else if (ch == NCHUNK - 2) CP_WAIT(1);
            else                       CP_WAIT(0);
        }
        __syncthreads();

        // C accumulators: [k-parity][4]; bias into parity 0 only.
        float c[2][4];
        c[0][0] = c[0][2] = bias0;
        c[0][1] = c[0][3] = bias1;
        c[1][0] = c[1][1] = c[1][2] = c[1][3] = 0.0f;

        const unsigned sbase =
            (unsigned)__cvta_generic_to_shared(buf) + row_local * 256;

        #pragma unroll
        for (int ks = 0; ks < 8; ks++) {
            unsigned raw[4];
            ldsm4(raw, sbase + (((2 * ks + hiu) ^ rxor) << 4));

            unsigned alo[4];
            #pragma unroll
            for (int j = 0; j < 4; j++) {
                float x  = __uint_as_float(raw[j]);
                float hi = __uint_as_float(__float_as_uint(x) & 0xFFFFE000u);
                alo[j] = __float_as_uint(x - hi);   // MMA truncates lo operand (~2^-21)
            }
            const int p = ks & 1;
            mma_tf32(c[p], alo, braw[ks][0], braw[ks][1]);   // lo x hi
            mma_tf32(c[p], raw, blo[ks][0],  blo[ks][1]);    // hi x lo
            mma_tf32(c[p], raw, braw[ks][0], braw[ks][1]);   // hi x hi
        }

        // ---- Epilogue for this m-tile: relu + dot with W_val (this warp's 8 cols)
        const int r1 = ch * CH_ROWS + rgrp * 16 + (lane >> 2);
        const int r2 = r1 + 8;
        const int n0 = 2 * (lane & 3) + 8 * nt;
        float2 w1 = __ldg(reinterpret_cast<const float2*>(W_val + r1 * EMB + n0));
        float2 w2 = __ldg(reinterpret_cast<const float2*>(W_val + r2 * EMB + n0));
        vpart += fmaxf(c[0][0] + c[1][0], 0.0f) * w1.x
               + fmaxf(c[0][1] + c[1][1], 0.0f) * w1.y
               + fmaxf(c[0][2] + c[1][2], 0.0f) * w2.x
               + fmaxf(c[0][3] + c[1][3], 0.0f) * w2.y;
        __syncthreads();            // chunk buffer fully consumed before reuse
    }

    // ---- Deterministic block reduction (8 warps)
    #pragma unroll
    for (int o = 16; o > 0; o >>= 1)
        vpart += __shfl_down_sync(0xffffffff, vpart, o);
    if (lane == 0) sred[warp] = vpart;
    __syncthreads();
    if (t == 0) {
        float v = (((sred[0] + sred[1]) + (sred[2] + sred[3]))
                 + ((sred[4] + sred[5]) + (sred[6] + sred[7]))) + b_val[0];
        out[(size_t)b * OUT_ROW + 1024] = v;
    }
}

extern "C" void kernel_launch(void* const* d_in, const int* in_sizes, int n_in,
                              void* d_out, int out_size)
{
    const float* x_gen = (const float*)d_in[0];
    const float* W_gen = (const float*)d_in[1];
    const float* b_gen = (const float*)d_in[2];
    const float* W_val = (const float*)d_in[3];
    const float* b_val = (const float*)d_in[4];
    const float* param = (const float*)d_in[5];
    const float* high  = (const float*)d_in[6];
    float* out = (float*)d_out;

    const int smem_bytes = (STAGES * CH_FLTS + 8) * sizeof(float);   // ~65.6 KB
    static bool attr_set = false;
    if (!attr_set) {
        cudaFuncSetAttribute(fused_model_kernel,
                             cudaFuncAttributeMaxDynamicSharedMemorySize, smem_bytes);
        attr_set = true;
    }

    fused_model_kernel<<<B_DIM, THREADS, smem_bytes>>>(
        x_gen, W_gen, b_gen, W_val, b_val, param, high, out);
}

// round 7
// speedup vs baseline: 1.0328x; 1.0328x over previous
#include <cuda_runtime.h>
#include <math.h>

#define B_DIM   4096
#define N_GENN  512
#define F_GEN   64
#define EMB     16
#define OUT_ROW 1025
#define THREADS 128
#define CH_ROWS 64            // x rows per staged chunk (16KB)
#define NCHUNK  8
#define STAGES  3
#define CH_FLTS (CH_ROWS * F_GEN)

__device__ __forceinline__ void mma_tf32(float c[4], const unsigned a[4],
                                         unsigned b0, unsigned b1) {
    asm volatile(
        "mma.sync.aligned.m16n8k8.row.col.f32.tf32.tf32.f32 "
        "{%0,%1,%2,%3}, {%4,%5,%6,%7}, {%8,%9}, {%0,%1,%2,%3};"
        : "+f"(c[0]), "+f"(c[1]), "+f"(c[2]), "+f"(c[3])
        : "r"(a[0]), "r"(a[1]), "r"(a[2]), "r"(a[3]), "r"(b0), "r"(b1));
}

__device__ __forceinline__ void ldsm4(unsigned r[4], unsigned addr) {
    asm volatile("ldmatrix.sync.aligned.m8n8.x4.shared.b16 {%0,%1,%2,%3}, [%4];"
                 : "=r"(r[0]), "=r"(r[1]), "=r"(r[2]), "=r"(r[3]) : "r"(addr));
}

__device__ __forceinline__ void cp16(void* smem_dst, const void* gsrc) {
    unsigned s = (unsigned)__cvta_generic_to_shared(smem_dst);
    asm volatile("cp.async.cg.shared.global [%0], [%1], 16;" :: "r"(s), "l"(gsrc));
}
#define CP_COMMIT() asm volatile("cp.async.commit_group;")
#define CP_WAIT(n)  asm volatile("cp.async.wait_group %0;" :: "n"(n))

// Stage one 64-row x chunk, 16B-unit XOR swizzle: unit j of row r -> slot j^(r&7).
// Conflict-free for both the cp.async stores and the ldmatrix gathers.
__device__ __forceinline__ void issue_chunk(float* sbuf, const float* gbase, int t) {
    #pragma unroll
    for (int k = 0; k < 8; k++) {
        int idx = t + THREADS * k;          // 0..1023 16B units
        int r = idx >> 4, j = idx & 15;
        int slot = j ^ (r & 7);
        cp16(&sbuf[r * 64 + slot * 4], gbase + r * 64 + j * 4);
    }
}

__global__ void __launch_bounds__(THREADS, 4)
fused_model_kernel(const float* __restrict__ x_gen,
                   const float* __restrict__ W_gen,
                   const float* __restrict__ b_gen,
                   const float* __restrict__ W_val,
                   const float* __restrict__ b_val,
                   const float* __restrict__ param,
                   const float* __restrict__ high,
                   float* __restrict__ out)
{
    __shared__ __align__(1024) float sX[STAGES][CH_FLTS];   // 3 x 16KB
    __shared__ float sred[32];

    const int b    = blockIdx.x;
    const int t    = threadIdx.x;
    const int warp = t >> 5;
    const int lane = t & 31;

    const float* gx = x_gen + (size_t)b * N_GENN * F_GEN;

    // ---- Preload chunks 0,1 immediately (prefetch distance 2)
    issue_chunk(sX[0], gx, t);                 CP_COMMIT();
    issue_chunk(sX[1], gx + CH_FLTS, t);       CP_COMMIT();

    // ---- Action head: out[b, 0..1023] (batch-independent, coalesced)
    {
        const float s0 = 1.0f / (1.0f + expf(-param[0]));
        const float s1 = 0.5f / (1.0f + expf(-param[1]));
        float* orow = out + (size_t)b * OUT_ROW;
        #pragma unroll
        for (int j = 0; j < 8; j++) {
            int i = t + THREADS * j;
            float h = __ldg(&high[i >> 1]);
            orow[i] = (i & 1) ? s1 * h : s0 * h;
        }
    }

    // ---- B fragments (both n-tiles per warp): raw fp32 (HW truncates -> hi) + lo.
    unsigned braw[2][8][2], blo[2][8][2];
    {
        const int kk = lane & 3, nn = lane >> 2;
        #pragma unroll
        for (int nt = 0; nt < 2; nt++)
            #pragma unroll
            for (int ks = 0; ks < 8; ks++)
                #pragma unroll
                for (int h = 0; h < 2; h++) {
                    float w = __ldg(&W_gen[(kk + 4 * h + 8 * ks) * EMB + nn + 8 * nt]);
                    unsigned whi = __float_as_uint(w) & 0xFFFFE000u;
                    braw[nt][ks][h] = __float_as_uint(w);
                    blo[nt][ks][h]  = __float_as_uint(w - __uint_as_float(whi));
                }
    }

    // ---- Bias for this thread's C columns: n = 2*(lane&3) + {0,1} + 8*nt
    float bias[2][2];
    #pragma unroll
    for (int nt = 0; nt < 2; nt++) {
        bias[nt][0] = __ldg(&b_gen[2 * (lane & 3) + 8 * nt]);
        bias[nt][1] = __ldg(&b_gen[2 * (lane & 3) + 8 * nt + 1]);
    }

    const int row_local = warp * 16 + (lane & 15);
    const int hiu       = lane >> 4;
    const int rxor      = row_local & 7;

    float vpart = 0.0f;

    // ---- Main pipeline: ONE barrier per chunk.
    //      wait(ch) -> barrier -> issue(ch+2) -> compute(ch) [+ epilogue, unfenced]
    #pragma unroll 1
    for (int ch = 0; ch < NCHUNK; ch++) {
        if      (ch <= NCHUNK - 3) CP_WAIT(1);   // groups ch..ch+1 in flight
        else if (ch == NCHUNK - 2) CP_WAIT(1);
        else                       CP_WAIT(0);
        __syncthreads();            // all warps done reading buffer (ch-1)%3

        if (ch + 2 < NCHUNK) {
            issue_chunk(sX[(ch + 2) % STAGES], gx + (ch + 2) * CH_FLTS, t);
            CP_COMMIT();
        }

        // C accumulators: [nt][k-parity][4]; bias into parity 0 only.
        float c[2][2][4];
        #pragma unroll
        for (int nt = 0; nt < 2; nt++) {
            c[nt][0][0] = c[nt][0][2] = bias[nt][0];
            c[nt][0][1] = c[nt][0][3] = bias[nt][1];
            c[nt][1][0] = c[nt][1][1] = c[nt][1][2] = c[nt][1][3] = 0.0f;
        }

        const unsigned sbase =
            (unsigned)__cvta_generic_to_shared(&sX[ch % STAGES][0]) + row_local * 256;

        #pragma unroll
        for (int ks = 0; ks < 8; ks++) {
            unsigned raw[4];
            ldsm4(raw, sbase + (((2 * ks + hiu) ^ rxor) << 4));

            unsigned alo[4];
            #pragma unroll
            for (int j = 0; j < 4; j++) {
                float x  = __uint_as_float(raw[j]);
                float hi = __uint_as_float(__float_as_uint(x) & 0xFFFFE000u);
                alo[j] = __float_as_uint(x - hi);   // MMA truncates lo operand (~2^-21)
            }
            const int p = ks & 1;
            #pragma unroll
            for (int nt = 0; nt < 2; nt++) {
                mma_tf32(c[nt][p], alo, braw[nt][ks][0], braw[nt][ks][1]);  // lo x hi
                mma_tf32(c[nt][p], raw, blo[nt][ks][0],  blo[nt][ks][1]);   // hi x lo
                mma_tf32(c[nt][p], raw, braw[nt][ks][0], braw[nt][ks][1]);  // hi x hi
            }
        }

        // ---- Epilogue: relu + dot with W_val (overlaps next step's wait)
        const int r1 = ch * CH_ROWS + warp * 16 + (lane >> 2);
        const int r2 = r1 + 8;
        #pragma unroll
        for (int nt = 0; nt < 2; nt++) {
            const int n0 = 2 * (lane & 3) + 8 * nt;
            float2 w1 = __ldg(reinterpret_cast<const float2*>(W_val + r1 * EMB + n0));
            float2 w2 = __ldg(reinterpret_cast<const float2*>(W_val + r2 * EMB + n0));
            vpart += fmaxf(c[nt][0][0] + c[nt][1][0], 0.0f) * w1.x
                   + fmaxf(c[nt][0][1] + c[nt][1][1], 0.0f) * w1.y
                   + fmaxf(c[nt][0][2] + c[nt][1][2], 0.0f) * w2.x
                   + fmaxf(c[nt][0][3] + c[nt][1][3], 0.0f) * w2.y;
        }
    }

    // ---- Deterministic block reduction (4 warps)
    #pragma unroll
    for (int o = 16; o > 0; o >>= 1)
        vpart += __shfl_down_sync(0xffffffff, vpart, o);
    if (lane == 0) sred[warp] = vpart;
    __syncthreads();
    if (t == 0) {
        float v = ((sred[0] + sred[1]) + (sred[2] + sred[3])) + b_val[0];
        out[(size_t)b * OUT_ROW + 1024] = v;
    }
}

extern "C" void kernel_launch(void* const* d_in, const int* in_sizes, int n_in,
                              void* d_out, int out_size)
{
    const float* x_gen = (const float*)d_in[0];
    const float* W_gen = (const float*)d_in[1];
    const float* b_gen = (const float*)d_in[2];
    const float* W_val = (const float*)d_in[3];
    const float* b_val = (const float*)d_in[4];
    const float* param = (const float*)d_in[5];
    const float* high  = (const float*)d_in[6];
    float* out = (float*)d_out;

    fused_model_kernel<<<B_DIM, THREADS>>>(
        x_gen, W_gen, b_gen, W_val, b_val, param, high, out);
}

// round 8
// speedup vs baseline: 1.0668x; 1.0329x over previous
#include <cuda_runtime.h>
#include <math.h>

#define B_DIM   4096
#define N_GENN  512
#define F_GEN   64
#define EMB     16
#define OUT_ROW 1025
#define THREADS 128
#define CH_ROWS 64            // x rows per staged chunk (16KB)
#define CH_PER_B 8            // chunks per batch
#define STAGES  3
#define CH_FLTS (CH_ROWS * F_GEN)
#define GRID    608           // 152 SMs x 4 CTAs: one persistent wave

__device__ __forceinline__ void mma_tf32(float c[4], const unsigned a[4],
                                         unsigned b0, unsigned b1) {
    asm volatile(
        "mma.sync.aligned.m16n8k8.row.col.f32.tf32.tf32.f32 "
        "{%0,%1,%2,%3}, {%4,%5,%6,%7}, {%8,%9}, {%0,%1,%2,%3};"
        : "+f"(c[0]), "+f"(c[1]), "+f"(c[2]), "+f"(c[3])
        : "r"(a[0]), "r"(a[1]), "r"(a[2]), "r"(a[3]), "r"(b0), "r"(b1));
}

__device__ __forceinline__ void ldsm4(unsigned r[4], unsigned addr) {
    asm volatile("ldmatrix.sync.aligned.m8n8.x4.shared.b16 {%0,%1,%2,%3}, [%4];"
                 : "=r"(r[0]), "=r"(r[1]), "=r"(r[2]), "=r"(r[3]) : "r"(addr));
}

__device__ __forceinline__ void cp16(void* smem_dst, const void* gsrc) {
    unsigned s = (unsigned)__cvta_generic_to_shared(smem_dst);
    asm volatile("cp.async.cg.shared.global [%0], [%1], 16;" :: "r"(s), "l"(gsrc));
}
#define CP_COMMIT() asm volatile("cp.async.commit_group;")
#define CP_WAIT(n)  asm volatile("cp.async.wait_group %0;" :: "n"(n))

// Stage one 64-row x chunk, 16B-unit XOR swizzle: unit j of row r -> slot j^(r&7).
__device__ __forceinline__ void issue_chunk(float* sbuf, const float* gbase, int t) {
    #pragma unroll
    for (int k = 0; k < 8; k++) {
        int idx = t + THREADS * k;          // 0..1023 16B units
        int r = idx >> 4, j = idx & 15;
        int slot = j ^ (r & 7);
        cp16(&sbuf[r * 64 + slot * 4], gbase + r * 64 + j * 4);
    }
}

__global__ void __launch_bounds__(THREADS, 4)
fused_model_kernel(const float* __restrict__ x_gen,
                   const float* __restrict__ W_gen,
                   const float* __restrict__ b_gen,
                   const float* __restrict__ W_val,
                   const float* __restrict__ b_val,
                   const float* __restrict__ param,
                   const float* __restrict__ high,
                   float* __restrict__ out)
{
    __shared__ __align__(1024) float sX[STAGES][CH_FLTS];   // 3 x 16KB
    __shared__ float sred[32];

    const int bid  = blockIdx.x;
    const int t    = threadIdx.x;
    const int warp = t >> 5;
    const int lane = t & 31;

    // Persistent work list: batches bid, bid+GRID, ... ; flat chunk stream.
    const int nb    = (B_DIM - 1 - bid) / GRID + 1;
    const int total = nb * CH_PER_B;

    // chunk i -> gmem base
    #define CPTR(i) (x_gen + (size_t)(bid + ((i) >> 3) * GRID) * (N_GENN * F_GEN) \
                           + ((i) & 7) * CH_FLTS)

    // ---- Fill pipeline once per CTA (prefetch distance 2)
    issue_chunk(sX[0], CPTR(0), t);    CP_COMMIT();
    issue_chunk(sX[1], CPTR(1), t);    CP_COMMIT();

    // ---- Action-head scales (persist in 2 regs)
    const float s0 = 1.0f / (1.0f + expf(-param[0]));
    const float s1 = 0.5f / (1.0f + expf(-param[1]));

    // ---- B fragments (both n-tiles per warp): raw fp32 (HW truncates -> hi) + lo.
    unsigned braw[2][8][2], blo[2][8][2];
    {
        const int kk = lane & 3, nn = lane >> 2;
        #pragma unroll
        for (int nt = 0; nt < 2; nt++)
            #pragma unroll
            for (int ks = 0; ks < 8; ks++)
                #pragma unroll
                for (int h = 0; h < 2; h++) {
                    float w = __ldg(&W_gen[(kk + 4 * h + 8 * ks) * EMB + nn + 8 * nt]);
                    unsigned whi = __float_as_uint(w) & 0xFFFFE000u;
                    braw[nt][ks][h] = __float_as_uint(w);
                    blo[nt][ks][h]  = __float_as_uint(w - __uint_as_float(whi));
                }
    }

    float bias[2][2];
    #pragma unroll
    for (int nt = 0; nt < 2; nt++) {
        bias[nt][0] = __ldg(&b_gen[2 * (lane & 3) + 8 * nt]);
        bias[nt][1] = __ldg(&b_gen[2 * (lane & 3) + 8 * nt + 1]);
    }

    const int row_local = warp * 16 + (lane & 15);
    const int hiu       = lane >> 4;
    const int rxor      = row_local & 7;

    float vpart = 0.0f;

    // ---- Persistent pipeline over all chunks of all assigned batches.
    //      R5 body: issue(i+2) -> commit -> wait(2) -> barrier -> compute -> barrier
    #pragma unroll 1
    for (int i = 0; i < total; i++) {
        const int ch   = i & 7;
        const int bcur = bid + (i >> 3) * GRID;

        if (i + 2 < total) {
            issue_chunk(sX[(i + 2) % STAGES], CPTR(i + 2), t);
            CP_COMMIT();
            CP_WAIT(2);                 // chunk i's group complete
        } else {
            if (i == total - 2) CP_WAIT(1);
            else                CP_WAIT(0);
        }
        __syncthreads();

        if (ch == 0) {
            // Action head for this batch (overlaps with compute's MMA waits)
            float* orow = out + (size_t)bcur * OUT_ROW;
            #pragma unroll
            for (int j = 0; j < 8; j++) {
                int idx = t + THREADS * j;
                float h = __ldg(&high[idx >> 1]);
                orow[idx] = (idx & 1) ? s1 * h : s0 * h;
            }
        }

        // C accumulators: [nt][k-parity][4]; bias into parity 0 only.
        float c[2][2][4];
        #pragma unroll
        for (int nt = 0; nt < 2; nt++) {
            c[nt][0][0] = c[nt][0][2] = bias[nt][0];
            c[nt][0][1] = c[nt][0][3] = bias[nt][1];
            c[nt][1][0] = c[nt][1][1] = c[nt][1][2] = c[nt][1][3] = 0.0f;
        }

        const unsigned sbase =
            (unsigned)__cvta_generic_to_shared(&sX[i % STAGES][0]) + row_local * 256;

        #pragma unroll
        for (int ks = 0; ks < 8; ks++) {
            unsigned raw[4];
            ldsm4(raw, sbase + (((2 * ks + hiu) ^ rxor) << 4));

            unsigned alo[4];
            #pragma unroll
            for (int j = 0; j < 4; j++) {
                float x  = __uint_as_float(raw[j]);
                float hi = __uint_as_float(__float_as_uint(x) & 0xFFFFE000u);
                alo[j] = __float_as_uint(x - hi);
            }
            const int p = ks & 1;
            #pragma unroll
            for (int nt = 0; nt < 2; nt++) {
                mma_tf32(c[nt][p], alo, braw[nt][ks][0], braw[nt][ks][1]);  // lo x hi
                mma_tf32(c[nt][p], raw, blo[nt][ks][0],  blo[nt][ks][1]);   // hi x lo
                mma_tf32(c[nt][p], raw, braw[nt][ks][0], braw[nt][ks][1]);  // hi x hi
            }
        }

        // ---- Epilogue: relu + dot with W_val
        const int r1 = ch * CH_ROWS + warp * 16 + (lane >> 2);
        const int r2 = r1 + 8;
        #pragma unroll
        for (int nt = 0; nt < 2; nt++) {
            const int n0 = 2 * (lane & 3) + 8 * nt;
            float2 w1 = __ldg(reinterpret_cast<const float2*>(W_val + r1 * EMB + n0));
            float2 w2 = __ldg(reinterpret_cast<const float2*>(W_val + r2 * EMB + n0));
            vpart += fmaxf(c[nt][0][0] + c[nt][1][0], 0.0f) * w1.x
                   + fmaxf(c[nt][0][1] + c[nt][1][1], 0.0f) * w1.y
                   + fmaxf(c[nt][0][2] + c[nt][1][2], 0.0f) * w2.x
                   + fmaxf(c[nt][0][3] + c[nt][1][3], 0.0f) * w2.y;
        }

        if (ch == 7) {                  // batch complete: cross-warp reduce
            #pragma unroll
            for (int o = 16; o > 0; o >>= 1)
                vpart += __shfl_down_sync(0xffffffff, vpart, o);
            if (lane == 0) sred[warp] = vpart;
            vpart = 0.0f;
        }
        __syncthreads();                // buffer consumed + sred visible

        if (ch == 7 && t == 0) {
            float v = ((sred[0] + sred[1]) + (sred[2] + sred[3])) + b_val[0];
            out[(size_t)bcur * OUT_ROW + 1024] = v;
        }
    }
    #undef CPTR
}

extern "C" void kernel_launch(void* const* d_in, const int* in_sizes, int n_in,
                              void* d_out, int out_size)
{
    const float* x_gen = (const float*)d_in[0];
    const float* W_gen = (const float*)d_in[1];
    const float* b_gen = (const float*)d_in[2];
    const float* W_val = (const float*)d_in[3];
    const float* b_val = (const float*)d_in[4];
    const float* param = (const float*)d_in[5];
    const float* high  = (const float*)d_in[6];
    float* out = (float*)d_out;

    fused_model_kernel<<<GRID, THREADS>>>(
        x_gen, W_gen, b_gen, W_val, b_val, param, high, out);
}

// round 9
// speedup vs baseline: 1.0895x; 1.0213x over previous
#include <cuda_runtime.h>
#include <math.h>

#define B_DIM   4096
#define N_GENN  512
#define F_GEN   64
#define EMB     16
#define OUT_ROW 1025
#define THREADS 128
#define CH_ROWS 64            // rows per chunk (16KB); 16 rows per warp
#define CH_PER_B 8
#define STAGES  3
#define CH_FLTS (CH_ROWS * F_GEN)     // 4096 floats
#define WR_FLTS (16 * F_GEN)          // 1024 floats per warp slice
#define GRID    608                   // 152 SMs x 4 CTAs: one persistent wave

__device__ __forceinline__ void mma_tf32(float c[4], const unsigned a[4],
                                         unsigned b0, unsigned b1) {
    asm volatile(
        "mma.sync.aligned.m16n8k8.row.col.f32.tf32.tf32.f32 "
        "{%0,%1,%2,%3}, {%4,%5,%6,%7}, {%8,%9}, {%0,%1,%2,%3};"
        : "+f"(c[0]), "+f"(c[1]), "+f"(c[2]), "+f"(c[3])
        : "r"(a[0]), "r"(a[1]), "r"(a[2]), "r"(a[3]), "r"(b0), "r"(b1));
}

__device__ __forceinline__ void ldsm4(unsigned r[4], unsigned addr) {
    asm volatile("ldmatrix.sync.aligned.m8n8.x4.shared.b16 {%0,%1,%2,%3}, [%4];"
                 : "=r"(r[0]), "=r"(r[1]), "=r"(r[2]), "=r"(r[3]) : "r"(addr));
}

__device__ __forceinline__ void cp16(void* smem_dst, const void* gsrc) {
    unsigned s = (unsigned)__cvta_generic_to_shared(smem_dst);
    asm volatile("cp.async.cg.shared.global [%0], [%1], 16;" :: "r"(s), "l"(gsrc));
}
#define CP_COMMIT() asm volatile("cp.async.commit_group;")
#define CP_WAIT(n)  asm volatile("cp.async.wait_group %0;" :: "n"(n))

// Warp-private staging: this warp loads ITS OWN 16 rows (4KB). Per iter,
// lanes 0-15 load one full 256B row, lanes 16-31 the next -> perfect coalescing.
// 16B-unit XOR swizzle (slot = j ^ (row&7)) keeps ldmatrix conflict-free.
__device__ __forceinline__ void issue_warp(float* wbuf, const float* gwarp, int lane) {
    const int j = lane & 15;
    #pragma unroll
    for (int k = 0; k < 8; k++) {
        int row = 2 * k + (lane >> 4);
        int slot = j ^ (row & 7);
        cp16(&wbuf[row * 64 + slot * 4], gwarp + row * 64 + j * 4);
    }
}

__global__ void __launch_bounds__(THREADS, 4)
fused_model_kernel(const float* __restrict__ x_gen,
                   const float* __restrict__ W_gen,
                   const float* __restrict__ b_gen,
                   const float* __restrict__ W_val,
                   const float* __restrict__ b_val,
                   const float* __restrict__ param,
                   const float* __restrict__ high,
                   float* __restrict__ out)
{
    __shared__ __align__(1024) float sX[STAGES][CH_FLTS];   // 3 x 16KB
    __shared__ float sred[32];                              // [batch][warp] partials

    const int bid  = blockIdx.x;
    const int t    = threadIdx.x;
    const int warp = t >> 5;
    const int lane = t & 31;

    // Persistent work list: batches bid, bid+GRID, ...; flat per-warp chunk stream.
    const int nb    = (B_DIM - 1 - bid) / GRID + 1;         // <= 7
    const int total = nb * CH_PER_B;

    // warp-slice gmem base for chunk i
    #define WPTR(i) (x_gen + (size_t)(bid + ((i) >> 3) * GRID) * (N_GENN * F_GEN) \
                           + ((i) & 7) * CH_FLTS + warp * WR_FLTS)

    float* wbuf0 = &sX[0][warp * WR_FLTS];
    float* wbuf1 = &sX[1][warp * WR_FLTS];

    // ---- Fill this warp's pipeline (prefetch distance 2)
    issue_warp(wbuf0, WPTR(0), lane);   CP_COMMIT();
    issue_warp(wbuf1, WPTR(1), lane);   CP_COMMIT();

    // ---- Action-head scales
    const float s0 = 1.0f / (1.0f + expf(-param[0]));
    const float s1 = 0.5f / (1.0f + expf(-param[1]));

    // ---- B fragments (both n-tiles per warp): raw fp32 (HW truncates -> hi) + lo.
    unsigned braw[2][8][2], blo[2][8][2];
    {
        const int kk = lane & 3, nn = lane >> 2;
        #pragma unroll
        for (int nt = 0; nt < 2; nt++)
            #pragma unroll
            for (int ks = 0; ks < 8; ks++)
                #pragma unroll
                for (int h = 0; h < 2; h++) {
                    float w = __ldg(&W_gen[(kk + 4 * h + 8 * ks) * EMB + nn + 8 * nt]);
                    unsigned whi = __float_as_uint(w) & 0xFFFFE000u;
                    braw[nt][ks][h] = __float_as_uint(w);
                    blo[nt][ks][h]  = __float_as_uint(w - __uint_as_float(whi));
                }
    }

    float bias[2][2];
    #pragma unroll
    for (int nt = 0; nt < 2; nt++) {
        bias[nt][0] = __ldg(&b_gen[2 * (lane & 3) + 8 * nt]);
        bias[nt][1] = __ldg(&b_gen[2 * (lane & 3) + 8 * nt + 1]);
    }

    const int hiu  = lane >> 4;
    const int rxor = (lane & 15) & 7;
    const unsigned lane_off = (lane & 15) * 256;

    float vpart = 0.0f;

    // ---- Per-warp pipeline: NO __syncthreads in the loop. Each warp is a fully
    //      independent stream: issue(i+2) -> wait own groups -> syncwarp -> compute.
    #pragma unroll 1
    for (int i = 0; i < total; i++) {
        const int ch = i & 7;

        if (i + 2 < total) {
            issue_warp(&sX[(i + 2) % STAGES][warp * WR_FLTS], WPTR(i + 2), lane);
            CP_COMMIT();
            CP_WAIT(2);                 // this warp's chunk i complete
        } else {
            if (i == total - 2) CP_WAIT(1);
            else                CP_WAIT(0);
        }
        __syncwarp();                   // warp-wide visibility of staged data

        if (ch == 0) {
            // Action head for this batch: each thread writes its own 8 slots.
            float* orow = out + (size_t)(bid + (i >> 3) * GRID) * OUT_ROW;
            #pragma unroll
            for (int j = 0; j < 8; j++) {
                int idx = t + THREADS * j;
                float h = __ldg(&high[idx >> 1]);
                orow[idx] = (idx & 1) ? s1 * h : s0 * h;
            }
        }

        // C accumulators: [nt][k-parity][4]; bias into parity 0 only.
        float c[2][2][4];
        #pragma unroll
        for (int nt = 0; nt < 2; nt++) {
            c[nt][0][0] = c[nt][0][2] = bias[nt][0];
            c[nt][0][1] = c[nt][0][3] = bias[nt][1];
            c[nt][1][0] = c[nt][1][1] = c[nt][1][2] = c[nt][1][3] = 0.0f;
        }

        const unsigned sbase =
            (unsigned)__cvta_generic_to_shared(&sX[i % STAGES][warp * WR_FLTS])
            + lane_off;

        #pragma unroll
        for (int ks = 0; ks < 8; ks++) {
            unsigned raw[4];
            ldsm4(raw, sbase + (((2 * ks + hiu) ^ rxor) << 4));

            unsigned alo[4];
            #pragma unroll
            for (int j = 0; j < 4; j++) {
                float x  = __uint_as_float(raw[j]);
                float hi = __uint_as_float(__float_as_uint(x) & 0xFFFFE000u);
                alo[j] = __float_as_uint(x - hi);   // MMA truncates lo (~2^-21)
            }
            const int p = ks & 1;
            #pragma unroll
            for (int nt = 0; nt < 2; nt++) {
                mma_tf32(c[nt][p], alo, braw[nt][ks][0], braw[nt][ks][1]);  // lo x hi
                mma_tf32(c[nt][p], raw, blo[nt][ks][0],  blo[nt][ks][1]);   // hi x lo
                mma_tf32(c[nt][p], raw, braw[nt][ks][0], braw[nt][ks][1]);  // hi x hi
            }
        }

        // ---- Epilogue: relu + dot with W_val (L2-resident)
        const int r1 = ch * CH_ROWS + warp * 16 + (lane >> 2);
        const int r2 = r1 + 8;
        #pragma unroll
        for (int nt = 0; nt < 2; nt++) {
            const int n0 = 2 * (lane & 3) + 8 * nt;
            float2 w1 = __ldg(reinterpret_cast<const float2*>(W_val + r1 * EMB + n0));
            float2 w2 = __ldg(reinterpret_cast<const float2*>(W_val + r2 * EMB + n0));
            vpart += fmaxf(c[nt][0][0] + c[nt][1][0], 0.0f) * w1.x
                   + fmaxf(c[nt][0][1] + c[nt][1][1], 0.0f) * w1.y
                   + fmaxf(c[nt][0][2] + c[nt][1][2], 0.0f) * w2.x
                   + fmaxf(c[nt][0][3] + c[nt][1][3], 0.0f) * w2.y;
        }

        if (ch == 7) {                  // batch done for this warp: park partial
            #pragma unroll
            for (int o = 16; o > 0; o >>= 1)
                vpart += __shfl_down_sync(0xffffffff, vpart, o);
            if (lane == 0) sred[(i >> 3) * 4 + warp] = vpart;
            vpart = 0.0f;
        }
    }

    // ---- Single block barrier: combine per-warp partials for all batches.
    __syncthreads();
    if (t < nb) {
        float v = ((sred[t * 4 + 0] + sred[t * 4 + 1])
                 + (sred[t * 4 + 2] + sred[t * 4 + 3])) + b_val[0];
        out[(size_t)(bid + t * GRID) * OUT_ROW + 1024] = v;
    }
    #undef WPTR
}

extern "C" void kernel_launch(void* const* d_in, const int* in_sizes, int n_in,
                              void* d_out, int out_size)
{
    const float* x_gen = (const float*)d_in[0];
    const float* W_gen = (const float*)d_in[1];
    const float* b_gen = (const float*)d_in[2];
    const float* W_val = (const float*)d_in[3];
    const float* b_val = (const float*)d_in[4];
    const float* param = (const float*)d_in[5];
    const float* high  = (const float*)d_in[6];
    float* out = (float*)d_out;

    fused_model_kernel<<<GRID, THREADS>>>(
        x_gen, W_gen, b_gen, W_val, b_val, param, high, out);
}

// round 10
// speedup vs baseline: 1.1211x; 1.0289x over previous
#include <cuda_runtime.h>
#include <cuda.h>
#include <math.h>

#define B_DIM   4096
#define N_GENN  512
#define F_GEN   64
#define EMB     16
#define OUT_ROW 1025
#define THREADS 128
#define CH_ROWS 64            // rows per chunk; 16 rows per warp
#define CH_PER_B 8
#define STAGES  3
#define WR_FLTS (16 * F_GEN)          // 1024 floats (4KB) per warp stage
#define GRID    608                   // 152 SMs x 4 CTAs persistent

// ---------------- shared device helpers ----------------

__device__ __forceinline__ void mma_tf32(float c[4], const unsigned a[4],
                                         unsigned b0, unsigned b1) {
    asm volatile(
        "mma.sync.aligned.m16n8k8.row.col.f32.tf32.tf32.f32 "
        "{%0,%1,%2,%3}, {%4,%5,%6,%7}, {%8,%9}, {%0,%1,%2,%3};"
        : "+f"(c[0]), "+f"(c[1]), "+f"(c[2]), "+f"(c[3])
        : "r"(a[0]), "r"(a[1]), "r"(a[2]), "r"(a[3]), "r"(b0), "r"(b1));
}

__device__ __forceinline__ void ldsm4(unsigned r[4], unsigned addr) {
    asm volatile("ldmatrix.sync.aligned.m8n8.x4.shared.b16 {%0,%1,%2,%3}, [%4];"
                 : "=r"(r[0]), "=r"(r[1]), "=r"(r[2]), "=r"(r[3]) : "r"(addr));
}

__device__ __forceinline__ unsigned s2u(const void* p) {
    return (unsigned)__cvta_generic_to_shared(p);
}

__device__ __forceinline__ void mbar_init(unsigned mb, unsigned cnt) {
    asm volatile("mbarrier.init.shared.b64 [%0], %1;" :: "r"(mb), "r"(cnt) : "memory");
}
__device__ __forceinline__ void mbar_expect_tx(unsigned mb, unsigned bytes) {
    asm volatile("mbarrier.arrive.expect_tx.shared.b64 _, [%0], %1;"
                 :: "r"(mb), "r"(bytes) : "memory");
}
__device__ __forceinline__ void mbar_wait(unsigned mb, unsigned parity) {
    asm volatile(
        "{\n\t"
        ".reg .pred P%=;\n\t"
        "W%=:\n\t"
        "mbarrier.try_wait.parity.acquire.cta.shared::cta.b64 P%=, [%0], %1, 0x989680;\n\t"
        "@P%= bra D%=;\n\t"
        "bra W%=;\n\t"
        "D%=:\n\t"
        "}"
        :: "r"(mb), "r"(parity) : "memory");
}
__device__ __forceinline__ void tma2d(unsigned dst, const CUtensorMap* m,
                                      int cx, int cy, unsigned mb) {
    asm volatile(
        "cp.async.bulk.tensor.2d.shared::cta.global.tile.mbarrier::complete_tx::bytes "
        "[%0], [%1, {%2, %3}], [%4];"
        :: "r"(dst), "l"(m), "r"(cx), "r"(cy), "r"(mb) : "memory");
}

// legacy cp.async (fallback kernel)
__device__ __forceinline__ void cp16(void* smem_dst, const void* gsrc) {
    asm volatile("cp.async.cg.shared.global [%0], [%1], 16;"
                 :: "r"(s2u(smem_dst)), "l"(gsrc));
}
#define CP_COMMIT() asm volatile("cp.async.commit_group;")
#define CP_WAIT(n)  asm volatile("cp.async.wait_group %0;" :: "n"(n))

// ================= TMA kernel =================
// Per-warp-private pipeline; x staged via 2x 2KB TMA box loads per 16-row tile.
// SMEM tile layout per warp stage (4KB): half h (cols 32h..32h+31) at +h*2048,
// row r at +r*128, 16B unit u stored at slot u^(r&7)  (TMA SWIZZLE_128B).
__global__ void __launch_bounds__(THREADS, 4)
fused_tma_kernel(const __grid_constant__ CUtensorMap tmap,
                 const float* __restrict__ W_gen,
                 const float* __restrict__ b_gen,
                 const float* __restrict__ W_val,
                 const float* __restrict__ b_val,
                 const float* __restrict__ param,
                 const float* __restrict__ high,
                 float* __restrict__ out)
{
    __shared__ __align__(1024) float sX[4][STAGES][WR_FLTS];   // 48KB
    __shared__ unsigned long long mbar[4][STAGES];
    __shared__ float sred[32];

    const int bid  = blockIdx.x;
    const int t    = threadIdx.x;
    const int warp = t >> 5;
    const int lane = t & 31;

    const int nb    = (B_DIM - 1 - bid) / GRID + 1;     // <= 7
    const int total = nb * CH_PER_B;

    // global x row for this warp's tile of chunk i
    #define WROW(i) ((bid + ((i) >> 3) * GRID) * N_GENN + ((i) & 7) * CH_ROWS + warp * 16)

    // ---- init this warp's mbarriers
    if (lane == 0) {
        #pragma unroll
        for (int s = 0; s < STAGES; s++) mbar_init(s2u(&mbar[warp][s]), 1);
    }
    asm volatile("fence.proxy.async.shared::cta;" ::: "memory");
    __syncwarp();

    // ---- issue chunks 0,1 (prefetch distance 2); issue-before-wait preserved
    #pragma unroll
    for (int s = 0; s < 2; s++) {
        if (lane == 0) {
            unsigned mb  = s2u(&mbar[warp][s]);
            unsigned dst = s2u(&sX[warp][s][0]);
            mbar_expect_tx(mb, 4096);
            tma2d(dst,        &tmap,  0, WROW(s), mb);
            tma2d(dst + 2048, &tmap, 32, WROW(s), mb);
        }
    }

    // ---- action-head scales
    const float s0 = 1.0f / (1.0f + expf(-param[0]));
    const float s1 = 0.5f / (1.0f + expf(-param[1]));

    // ---- B fragments (both n-tiles per warp): raw fp32 (HW truncates -> hi) + lo
    unsigned braw[2][8][2], blo[2][8][2];
    {
        const int kk = lane & 3, nn = lane >> 2;
        #pragma unroll
        for (int nt = 0; nt < 2; nt++)
            #pragma unroll
            for (int ks = 0; ks < 8; ks++)
                #pragma unroll
                for (int h = 0; h < 2; h++) {
                    float w = __ldg(&W_gen[(kk + 4 * h + 8 * ks) * EMB + nn + 8 * nt]);
                    unsigned whi = __float_as_uint(w) & 0xFFFFE000u;
                    braw[nt][ks][h] = __float_as_uint(w);
                    blo[nt][ks][h]  = __float_as_uint(w - __uint_as_float(whi));
                }
    }
    float bias[2][2];
    #pragma unroll
    for (int nt = 0; nt < 2; nt++) {
        bias[nt][0] = __ldg(&b_gen[2 * (lane & 3) + 8 * nt]);
        bias[nt][1] = __ldg(&b_gen[2 * (lane & 3) + 8 * nt + 1]);
    }

    const int hiu  = lane >> 4;
    const int r15  = lane & 15;
    const int rxor = r15 & 7;

    float vpart = 0.0f;

    #pragma unroll 1
    for (int i = 0; i < total; i++) {
        const int ch = i & 7;

        if (i + 2 < total && lane == 0) {       // issue i+2 BEFORE waiting on i
            const int s = (i + 2) % STAGES;
            unsigned mb  = s2u(&mbar[warp][s]);
            unsigned dst = s2u(&sX[warp][s][0]);
            mbar_expect_tx(mb, 4096);
            tma2d(dst,        &tmap,  0, WROW(i + 2), mb);
            tma2d(dst + 2048, &tmap, 32, WROW(i + 2), mb);
        }
        mbar_wait(s2u(&mbar[warp][i % STAGES]), (unsigned)((i / STAGES) & 1));

        if (ch == 0) {                          // action head for this batch
            float* orow = out + (size_t)(bid + (i >> 3) * GRID) * OUT_ROW;
            #pragma unroll
            for (int j = 0; j < 8; j++) {
                int idx = t + THREADS * j;
                float h = __ldg(&high[idx >> 1]);
                orow[idx] = (idx & 1) ? s1 * h : s0 * h;
            }
        }

        // C accumulators: [nt][k-parity][4]; bias into parity 0 only.
        float c[2][2][4];
        #pragma unroll
        for (int nt = 0; nt < 2; nt++) {
            c[nt][0][0] = c[nt][0][2] = bias[nt][0];
            c[nt][0][1] = c[nt][0][3] = bias[nt][1];
            c[nt][1][0] = c[nt][1][1] = c[nt][1][2] = c[nt][1][3] = 0.0f;
        }

        const unsigned sbase = s2u(&sX[warp][i % STAGES][0]) + r15 * 128;

        #pragma unroll
        for (int ks = 0; ks < 8; ks++) {
            const int U = 2 * ks + hiu;
            unsigned raw[4];
            ldsm4(raw, sbase + (U >> 3) * 2048 + (((U & 7) ^ rxor) << 4));

            unsigned alo[4];
            #pragma unroll
            for (int j = 0; j < 4; j++) {
                float x  = __uint_as_float(raw[j]);
                float hi = __uint_as_float(__float_as_uint(x) & 0xFFFFE000u);
                alo[j] = __float_as_uint(x - hi);
            }
            const int p = ks & 1;
            #pragma unroll
            for (int nt = 0; nt < 2; nt++) {
                mma_tf32(c[nt][p], alo, braw[nt][ks][0], braw[nt][ks][1]);  // lo x hi
                mma_tf32(c[nt][p], raw, blo[nt][ks][0],  blo[nt][ks][1]);   // hi x lo
                mma_tf32(c[nt][p], raw, braw[nt][ks][0], braw[nt][ks][1]);  // hi x hi
            }
        }

        // ---- Epilogue: relu + dot with W_val (L2-resident)
        const int r1 = ch * CH_ROWS + warp * 16 + (lane >> 2);
        const int r2 = r1 + 8;
        #pragma unroll
        for (int nt = 0; nt < 2; nt++) {
            const int n0 = 2 * (lane & 3) + 8 * nt;
            float2 w1 = __ldg(reinterpret_cast<const float2*>(W_val + r1 * EMB + n0));
            float2 w2 = __ldg(reinterpret_cast<const float2*>(W_val + r2 * EMB + n0));
            vpart += fmaxf(c[nt][0][0] + c[nt][1][0], 0.0f) * w1.x
                   + fmaxf(c[nt][0][1] + c[nt][1][1], 0.0f) * w1.y
                   + fmaxf(c[nt][0][2] + c[nt][1][2], 0.0f) * w2.x
                   + fmaxf(c[nt][0][3] + c[nt][1][3], 0.0f) * w2.y;
        }

        if (ch == 7) {
            #pragma unroll
            for (int o = 16; o > 0; o >>= 1)
                vpart += __shfl_down_sync(0xffffffff, vpart, o);
            if (lane == 0) sred[(i >> 3) * 4 + warp] = vpart;
            vpart = 0.0f;
        }
    }

    __syncthreads();
    if (t < nb) {
        float v = ((sred[t * 4 + 0] + sred[t * 4 + 1])
                 + (sred[t * 4 + 2] + sred[t * 4 + 3])) + b_val[0];
        out[(size_t)(bid + t * GRID) * OUT_ROW + 1024] = v;
    }
    #undef WROW
}

// ================= fallback kernel (proven R9 cp.async path) =================
#define CH_FLTS (CH_ROWS * F_GEN)

__device__ __forceinline__ void issue_warp(float* wbuf, const float* gwarp, int lane) {
    const int j = lane & 15;
    #pragma unroll
    for (int k = 0; k < 8; k++) {
        int row = 2 * k + (lane >> 4);
        int slot = j ^ (row & 7);
        cp16(&wbuf[row * 64 + slot * 4], gwarp + row * 64 + j * 4);
    }
}

__global__ void __launch_bounds__(THREADS, 4)
fused_model_kernel(const float* __restrict__ x_gen,
                   const float* __restrict__ W_gen,
                   const float* __restrict__ b_gen,
                   const float* __restrict__ W_val,
                   const float* __restrict__ b_val,
                   const float* __restrict__ param,
                   const float* __restrict__ high,
                   float* __restrict__ out)
{
    __shared__ __align__(1024) float sX[STAGES][CH_FLTS];
    __shared__ float sred[32];

    const int bid  = blockIdx.x;
    const int t    = threadIdx.x;
    const int warp = t >> 5;
    const int lane = t & 31;

    const int nb    = (B_DIM - 1 - bid) / GRID + 1;
    const int total = nb * CH_PER_B;

    #define WPTR(i) (x_gen + (size_t)(bid + ((i) >> 3) * GRID) * (N_GENN * F_GEN) \
                           + ((i) & 7) * CH_FLTS + warp * WR_FLTS)

    issue_warp(&sX[0][warp * WR_FLTS], WPTR(0), lane);   CP_COMMIT();
    issue_warp(&sX[1][warp * WR_FLTS], WPTR(1), lane);   CP_COMMIT();

    const float s0 = 1.0f / (1.0f + expf(-param[0]));
    const float s1 = 0.5f / (1.0f + expf(-param[1]));

    unsigned braw[2][8][2], blo[2][8][2];
    {
        const int kk = lane & 3, nn = lane >> 2;
        #pragma unroll
        for (int nt = 0; nt < 2; nt++)
            #pragma unroll
            for (int ks = 0; ks < 8; ks++)
                #pragma unroll
                for (int h = 0; h < 2; h++) {
                    float w = __ldg(&W_gen[(kk + 4 * h + 8 * ks) * EMB + nn + 8 * nt]);
                    unsigned whi = __float_as_uint(w) & 0xFFFFE000u;
                    braw[nt][ks][h] = __float_as_uint(w);
                    blo[nt][ks][h]  = __float_as_uint(w - __uint_as_float(whi));
                }
    }
    float bias[2][2];
    #pragma unroll
    for (int nt = 0; nt < 2; nt++) {
        bias[nt][0] = __ldg(&b_gen[2 * (lane & 3) + 8 * nt]);
        bias[nt][1] = __ldg(&b_gen[2 * (lane & 3) + 8 * nt + 1]);
    }

    const int hiu  = lane >> 4;
    const int rxor = (lane & 15) & 7;
    const unsigned lane_off = (lane & 15) * 256;

    float vpart = 0.0f;

    #pragma unroll 1
    for (int i = 0; i < total; i++) {
        const int ch = i & 7;
        if (i + 2 < total) {
            issue_warp(&sX[(i + 2) % STAGES][warp * WR_FLTS], WPTR(i + 2), lane);
            CP_COMMIT();
            CP_WAIT(2);
        } else {
            if (i == total - 2) CP_WAIT(1);
            else                CP_WAIT(0);
        }
        __syncwarp();

        if (ch == 0) {
            float* orow = out + (size_t)(bid + (i >> 3) * GRID) * OUT_ROW;
            #pragma unroll
            for (int j = 0; j < 8; j++) {
                int idx = t + THREADS * j;
                float h = __ldg(&high[idx >> 1]);
                orow[idx] = (idx & 1) ? s1 * h : s0 * h;
            }
        }

        float c[2][2][4];
        #pragma unroll
        for (int nt = 0; nt < 2; nt++) {
            c[nt][0][0] = c[nt][0][2] = bias[nt][0];
            c[nt][0][1] = c[nt][0][3] = bias[nt][1];
            c[nt][1][0] = c[nt][1][1] = c[nt][1][2] = c[nt][1][3] = 0.0f;
        }

        const unsigned sbase = s2u(&sX[i % STAGES][warp * WR_FLTS]) + lane_off;

        #pragma unroll
        for (int ks = 0; ks < 8; ks++) {
            unsigned raw[4];
            ldsm4(raw, sbase + (((2 * ks + hiu) ^ rxor) << 4));
            unsigned alo[4];
            #pragma unroll
            for (int j = 0; j < 4; j++) {
                float x  = __uint_as_float(raw[j]);
                float hi = __uint_as_float(__float_as_uint(x) & 0xFFFFE000u);
                alo[j] = __float_as_uint(x - hi);
            }
            const int p = ks & 1;
            #pragma unroll
            for (int nt = 0; nt < 2; nt++) {
                mma_tf32(c[nt][p], alo, braw[nt][ks][0], braw[nt][ks][1]);
                mma_tf32(c[nt][p], raw, blo[nt][ks][0],  blo[nt][ks][1]);
                mma_tf32(c[nt][p], raw, braw[nt][ks][0], braw[nt][ks][1]);
            }
        }

        const int r1 = ch * CH_ROWS + warp * 16 + (lane >> 2);
        const int r2 = r1 + 8;
        #pragma unroll
        for (int nt = 0; nt < 2; nt++) {
            const int n0 = 2 * (lane & 3) + 8 * nt;
            float2 w1 = __ldg(reinterpret_cast<const float2*>(W_val + r1 * EMB + n0));
            float2 w2 = __ldg(reinterpret_cast<const float2*>(W_val + r2 * EMB + n0));
            vpart += fmaxf(c[nt][0][0] + c[nt][1][0], 0.0f) * w1.x
                   + fmaxf(c[nt][0][1] + c[nt][1][1], 0.0f) * w1.y
                   + fmaxf(c[nt][0][2] + c[nt][1][2], 0.0f) * w2.x
                   + fmaxf(c[nt][0][3] + c[nt][1][3], 0.0f) * w2.y;
        }

        if (ch == 7) {
            #pragma unroll
            for (int o = 16; o > 0; o >>= 1)
                vpart += __shfl_down_sync(0xffffffff, vpart, o);
            if (lane == 0) sred[(i >> 3) * 4 + warp] = vpart;
            vpart = 0.0f;
        }
    }

    __syncthreads();
    if (t < nb) {
        float v = ((sred[t * 4 + 0] + sred[t * 4 + 1])
                 + (sred[t * 4 + 2] + sred[t * 4 + 3])) + b_val[0];
        out[(size_t)(bid + t * GRID) * OUT_ROW + 1024] = v;
    }
    #undef WPTR
}

// ================= host =================

typedef CUresult (*PFN_encodeTiled)(
    CUtensorMap*, CUtensorMapDataType, cuuint32_t, void*,
    const cuuint64_t*, const cuuint64_t*, const cuuint32_t*, const cuuint32_t*,
    CUtensorMapInterleave, CUtensorMapSwizzle, CUtensorMapL2promotion,
    CUtensorMapFloatOOBfill);

extern "C" void kernel_launch(void* const* d_in, const int* in_sizes, int n_in,
                              void* d_out, int out_size)
{
    const float* x_gen = (const float*)d_in[0];
    const float* W_gen = (const float*)d_in[1];
    const float* b_gen = (const float*)d_in[2];
    const float* W_val = (const float*)d_in[3];
    const float* b_val = (const float*)d_in[4];
    const float* param = (const float*)d_in[5];
    const float* high  = (const float*)d_in[6];
    float* out = (float*)d_out;

    static PFN_encodeTiled enc = nullptr;
    static bool probed = false;
    if (!probed) {
        probed = true;
        void* p = nullptr;
        cudaDriverEntryPointQueryResult qr;
        if (cudaGetDriverEntryPoint("cuTensorMapEncodeTiled", &p,
                                    cudaEnableDefault, &qr) == cudaSuccess &&
            qr == cudaDriverEntryPointSuccess)
            enc = (PFN_encodeTiled)p;
    }

    if (enc) {
        CUtensorMap tmap;
        cuuint64_t gdim[2]    = {F_GEN, (cuuint64_t)B_DIM * N_GENN};
        cuuint64_t gstride[1] = {F_GEN * sizeof(float)};
        cuuint32_t box[2]     = {32, 16};
        cuuint32_t estr[2]    = {1, 1};
        CUresult r = enc(&tmap, CU_TENSOR_MAP_DATA_TYPE_FLOAT32, 2, (void*)x_gen,
                         gdim, gstride, box, estr,
                         CU_TENSOR_MAP_INTERLEAVE_NONE, CU_TENSOR_MAP_SWIZZLE_128B,
                         CU_TENSOR_MAP_L2_PROMOTION_L2_128B,
                         CU_TENSOR_MAP_FLOAT_OOB_FILL_NONE);
        if (r == CUDA_SUCCESS) {
            fused_tma_kernel<<<GRID, THREADS>>>(
                tmap, W_gen, b_gen, W_val, b_val, param, high, out);
            return;
        }
    }
    fused_model_kernel<<<GRID, THREADS>>>(
        x_gen, W_gen, b_gen, W_val, b_val, param, high, out);
}